// round 11
// baseline (speedup 1.0000x reference)
#include <cuda_runtime.h>
#include <cstdint>

// ItemCodeDPQ: out[b,s,m*16+d] = centroids[m, clamp(item_codes[input_ids[b,s], m],0,255), d]
//              zeroed where input_ids[b,s] == 0.  input_ids arrive as int32.
//
// R11: TMA bulk-store experiment. Gathers come from the smem-staged 128KB
// centroid table; each warp stages 4 tokens (2KB) into a double-buffered smem
// slice and drains it with cp.async.bulk (shared::cta -> global, bulk_group),
// bypassing the per-thread STG path entirely.
// smem: 131072 (table) + 16 warps * 2 * 2048 (staging) = 196608 B.

#define CENT_F4 8192
#define TABLE_BYTES 131072
#define CHUNK 4                       // tokens per staged buffer
#define STAGE_BYTES (CHUNK * 512)     // 2048
#define WARPS_PER_CTA 16

__global__ void __launch_bounds__(512, 1)
itemcode_dpq_tma_kernel(const int* __restrict__ input_ids,
                        const int* __restrict__ item_codes,
                        const float4* __restrict__ centroids4,
                        float4* __restrict__ out4,
                        int ntok)
{
    extern __shared__ char smem_raw[];
    float4* s_cent = (float4*)smem_raw;

    // cooperative centroid table load
    #pragma unroll
    for (int i = threadIdx.x; i < CENT_F4; i += 512)
        s_cent[i] = centroids4[i];
    __syncthreads();

    const unsigned lane = threadIdx.x & 31u;
    const unsigned sub  = lane >> 2;           // 0..7
    const unsigned part = lane & 3u;           // 0..3
    const unsigned wic  = threadIdx.x >> 5;    // warp in CTA, 0..15

    // per-warp double-buffered staging slice
    char* my_stage = smem_raw + TABLE_BYTES + wic * (2 * STAGE_BYTES);
    const unsigned stage_base =
        (unsigned)__cvta_generic_to_shared(my_stage);

    const unsigned gwarp  = blockIdx.x * WARPS_PER_CTA + wic;
    const unsigned nwarp  = gridDim.x * WARPS_PER_CTA;
    const unsigned nchunk = (unsigned)ntok / CHUNK;   // ntok % 4 == 0

    unsigned iter = 0;
    for (unsigned ch = gwarp; ch < nchunk; ch += nwarp, iter++) {
        const unsigned t0    = ch * CHUNK;
        const unsigned stage = stage_base + (iter & 1u) * STAGE_BYTES;

        // ensure the buffer we're about to overwrite (issued 2 iters ago)
        // has been fully read by TMA
        if (lane == 0)
            asm volatile("cp.async.bulk.wait_group 1;" ::: "memory");
        __syncwarp();

        // ---- Phase A: resolve codes (independent id->code chains) ----
        int c[CHUNK];
        unsigned zmask = 0u;
        #pragma unroll
        for (int j = 0; j < CHUNK; j++) {
            const unsigned id = (unsigned)__ldg(&input_ids[t0 + (unsigned)j]);
            c[j] = __ldg(&item_codes[id * 8u + sub]);
            zmask |= (id == 0u) ? (1u << j) : 0u;
        }

        // ---- Phase B: smem gather -> stage into smem (STS.128) ----
        #pragma unroll
        for (int j = 0; j < CHUNK; j++) {
            const unsigned code = (unsigned)min(max(c[j], 0), 255);
            float4 v = s_cent[(sub * 256u + code) * 4u + part];
            if ((zmask >> j) & 1u) v = make_float4(0.f, 0.f, 0.f, 0.f);
            const unsigned dst = stage + (unsigned)j * 512u + lane * 16u;
            asm volatile("st.shared.v4.b32 [%0], {%1, %2, %3, %4};"
                         :: "r"(dst), "r"(__float_as_uint(v.x)),
                            "r"(__float_as_uint(v.y)),
                            "r"(__float_as_uint(v.z)),
                            "r"(__float_as_uint(v.w)) : "memory");
        }
        __syncwarp();

        // ---- TMA bulk store: 2KB smem -> global ----
        if (lane == 0) {
            asm volatile("fence.proxy.async.shared::cta;" ::: "memory");
            const float4* gdst = out4 + (size_t)t0 * 32u;
            asm volatile(
                "cp.async.bulk.global.shared::cta.bulk_group [%0], [%1], %2;"
                :: "l"(gdst), "r"(stage), "n"(STAGE_BYTES) : "memory");
            asm volatile("cp.async.bulk.commit_group;" ::: "memory");
        }
    }

    // drain all outstanding bulk stores before CTA exit
    if (lane == 0)
        asm volatile("cp.async.bulk.wait_group 0;" ::: "memory");
    __syncwarp();
}

extern "C" void kernel_launch(void* const* d_in, const int* in_sizes, int n_in,
                              void* d_out, int out_size)
{
    const int*    input_ids  = (const int*)d_in[0];     // (1024,200) int32
    const int*    item_codes = (const int*)d_in[1];     // (1e6, 8) int32
    const float4* centroids  = (const float4*)d_in[2];  // (8,256,16) fp32
    float4*       out        = (float4*)d_out;          // (1024,200,128) fp32

    const int ntok = in_sizes[0];   // 204800

    const int smem_bytes = TABLE_BYTES + WARPS_PER_CTA * 2 * STAGE_BYTES; // 196608
    cudaFuncSetAttribute(itemcode_dpq_tma_kernel,
                         cudaFuncAttributeMaxDynamicSharedMemorySize, smem_bytes);

    int nsm = 148;
    cudaDeviceGetAttribute(&nsm, cudaDevAttrMultiProcessorCount, 0);

    itemcode_dpq_tma_kernel<<<nsm, 512, smem_bytes>>>(input_ids, item_codes,
                                                      centroids, out, ntok);
}

// round 12
// speedup vs baseline: 1.4981x; 1.4981x over previous
#include <cuda_runtime.h>
#include <cstdint>

// ItemCodeDPQ: out[b,s,m*16+d] = centroids[m, clamp(item_codes[input_ids[b,s], m],0,255), d]
//              zeroed where input_ids[b,s] == 0.  input_ids arrive as int32.
//
// R12: hybrid gather. Sub-codebooks 0..3 (64KB) staged in smem; lanes 0..15
// gather via LDS (no replay tax), lanes 16..31 gather via L1 (hot set now
// 64KB -> resident, replays halved). 64KB smem keeps 3 CTAs/SM (75% occ).
// Rolling 16-token-per-warp structure from R6; shuffle-free; __stcs stores.

#define HALF_F4 4096   // subs 0..3 : 4*256*16 floats / 4 = 65536 B

__global__ void __launch_bounds__(512)
itemcode_dpq_kernel(const int* __restrict__ input_ids,
                    const int* __restrict__ item_codes,
                    const float4* __restrict__ centroids4,
                    float4* __restrict__ out4,
                    int ntok)
{
    extern __shared__ float4 s_cent[];   // [4096] = subs 0..3

    #pragma unroll
    for (int i = threadIdx.x; i < HALF_F4; i += 512)
        s_cent[i] = centroids4[i];
    __syncthreads();

    const unsigned lane = threadIdx.x & 31u;
    const unsigned sub  = lane >> 2;          // 0..7 : sub-codebook this lane serves
    const unsigned part = lane & 3u;          // 0..3 : float4 within 16-float sub-emb
    const bool use_smem = (sub < 4u);

    const unsigned warp = (blockIdx.x * blockDim.x + threadIdx.x) >> 5;
    const unsigned t0   = warp * 16u;
    if (t0 >= (unsigned)ntok) return;         // ntok = 204800, divisible by 16

    #pragma unroll
    for (int j = 0; j < 16; j++) {
        const unsigned t  = t0 + (unsigned)j;
        const unsigned id = (unsigned)__ldg(&input_ids[t]);
        int code = __ldg(&item_codes[id * 8u + sub]);
        code = min(max(code, 0), 255);

        const unsigned idx = (sub * 256u + (unsigned)code) * 4u + part;
        float4 v;
        if (use_smem) {
            v = s_cent[idx];                   // lanes 0..15: LDS, subs 0..3
        } else {
            v = __ldg(&centroids4[idx]);       // lanes 16..31: L1, subs 4..7
        }
        if (id == 0u) v = make_float4(0.f, 0.f, 0.f, 0.f);
        __stcs(&out4[t * 32u + lane], v);
    }
}

extern "C" void kernel_launch(void* const* d_in, const int* in_sizes, int n_in,
                              void* d_out, int out_size)
{
    const int*    input_ids  = (const int*)d_in[0];     // (1024,200) int32
    const int*    item_codes = (const int*)d_in[1];     // (1e6, 8) int32
    const float4* centroids  = (const float4*)d_in[2];  // (8,256,16) fp32
    float4*       out        = (float4*)d_out;          // (1024,200,128) fp32

    const int ntok = in_sizes[0];   // 204800

    cudaFuncSetAttribute(itemcode_dpq_kernel,
                         cudaFuncAttributeMaxDynamicSharedMemorySize, 65536);

    // 16 tokens per warp, 16 warps per 512-thread CTA => 256 tokens per CTA
    int warps = (ntok + 15) / 16;
    int ctas  = (warps + 15) / 16;
    itemcode_dpq_kernel<<<ctas, 512, 65536>>>(input_ids, item_codes, centroids,
                                              out, ntok);
}

// round 13
// speedup vs baseline: 1.5134x; 1.0102x over previous
#include <cuda_runtime.h>
#include <cstdint>

// ItemCodeDPQ: out[b,s,m*16+d] = centroids[m, clamp(item_codes[input_ids[b,s], m],0,255), d]
//              zeroed where input_ids[b,s] == 0.  input_ids arrive as int32.
//
// R13: full 128KB centroid table in smem, TRANSPOSED to [code][sub][part]
// (f4idx = code*32 + lane) so every 8 consecutive lanes cover all 32 banks
// -> provably conflict-free LDS.128 gathers regardless of code values.
// Gathers leave the L1tex path entirely (no replay tax); L1tex carries only
// stores + code loads. 1024-thread persistent CTAs, 16-token rolling chains.

#define CENT_F4 8192   // 8*256*16 floats / 4 = 131072 bytes

__global__ void __launch_bounds__(1024, 1)
itemcode_dpq_kernel(const int* __restrict__ input_ids,
                    const int* __restrict__ item_codes,
                    const float4* __restrict__ centroids4,
                    float4* __restrict__ out4,
                    int ntok)
{
    extern __shared__ float4 s_cent[];   // [256][8][4] = [code][sub][part]

    // cooperative transposed table load:
    // global f4idx = (sub*256 + code)*4 + part  ->  smem f4idx = code*32 + sub*4 + part
    for (int i = threadIdx.x; i < CENT_F4; i += 1024) {
        const int part = i & 3;
        const int code = (i >> 2) & 255;
        const int sub  = i >> 10;
        s_cent[code * 32 + sub * 4 + part] = centroids4[i];
    }
    __syncthreads();

    const unsigned lane = threadIdx.x & 31u;
    const unsigned sub  = lane >> 2;          // 0..7 : sub-codebook this lane serves

    const unsigned warp   = (blockIdx.x * 1024u + threadIdx.x) >> 5;
    const unsigned nwarp  = gridDim.x * 32u;
    const unsigned nchunk = (unsigned)ntok >> 4;      // ntok divisible by 16

    for (unsigned ch = warp; ch < nchunk; ch += nwarp) {
        const unsigned t0 = ch * 16u;
        #pragma unroll
        for (int j = 0; j < 16; j++) {
            const unsigned t  = t0 + (unsigned)j;
            const unsigned id = (unsigned)__ldg(&input_ids[t]);
            int code = __ldg(&item_codes[id * 8u + sub]);   // 1 sector/warp/token
            code = min(max(code, 0), 255);

            // conflict-free gather: f4idx = code*32 + lane
            float4 v = s_cent[(unsigned)code * 32u + lane];
            if (id == 0u) v = make_float4(0.f, 0.f, 0.f, 0.f);
            __stcs(&out4[t * 32u + lane], v);
        }
    }
}

extern "C" void kernel_launch(void* const* d_in, const int* in_sizes, int n_in,
                              void* d_out, int out_size)
{
    const int*    input_ids  = (const int*)d_in[0];     // (1024,200) int32
    const int*    item_codes = (const int*)d_in[1];     // (1e6, 8) int32
    const float4* centroids  = (const float4*)d_in[2];  // (8,256,16) fp32
    float4*       out        = (float4*)d_out;          // (1024,200,128) fp32

    const int ntok = in_sizes[0];   // 204800

    cudaFuncSetAttribute(itemcode_dpq_kernel,
                         cudaFuncAttributeMaxDynamicSharedMemorySize, 131072);

    int nsm = 148;
    cudaDeviceGetAttribute(&nsm, cudaDevAttrMultiProcessorCount, 0);

    itemcode_dpq_kernel<<<nsm, 1024, 131072>>>(input_ids, item_codes, centroids,
                                               out, ntok);
}